// round 17
// baseline (speedup 1.0000x reference)
#include <cuda_runtime.h>
#include <math.h>

#define NB 128
#define D_IMG 8192
#define D_LANG 4096
#define NCH 32            // chunks per matrix: img KC=256, lang KC=128
#define GRID 64           // 32 img + 32 lang blocks, all co-resident
#define NT 512
// smem: two packed-bf16 tiles [128][stride=132 words] (img case)
#define SMEM_TOTAL (2 * 128 * 132 * 4)

// ---------- scratch (static device memory; no allocations) ----------
__device__ float d_part_img[NCH * NB * NB];
__device__ float d_part_lang[NCH * NB * NB];
__device__ float d_diag[2][NCH][NB];
__device__ float d_pre[2 * NB * NB];
__device__ float d_lse[2 * NB];
__device__ unsigned g_count[2];
__device__ volatile unsigned g_phase[2];

// pack two floats into bf16x2 (x -> low half, y -> high half)
__device__ __forceinline__ unsigned pack_bf16(float x, float y) {
    unsigned w;
    asm("cvt.rn.bf16x2.f32 %0, %1, %2;" : "=r"(w) : "f"(y), "f"(x));
    return w;
}

#define MMAB(C, A, B0, B1)                                                    \
    asm volatile("mma.sync.aligned.m16n8k16.row.col.f32.bf16.bf16.f32 "       \
                 "{%0,%1,%2,%3}, {%4,%5,%6,%7}, {%8,%9}, {%0,%1,%2,%3};"      \
                 : "+f"(C[0]), "+f"(C[1]), "+f"(C[2]), "+f"(C[3])             \
                 : "r"(A[0]), "r"(A[1]), "r"(A[2]), "r"(A[3]),                 \
                   "r"(B0), "r"(B1))

// sense-reversing grid barrier; all GRID blocks are co-resident
__device__ __forceinline__ void grid_bar(int id) {
    __syncthreads();
    if (threadIdx.x == 0) {
        __threadfence();
        unsigned p = g_phase[id];
        unsigned old = atomicAdd(&g_count[id], 1);
        if (old == GRID - 1) {
            g_count[id] = 0;
            __threadfence();
            g_phase[id] = p + 1;
        } else {
            while (g_phase[id] == p) {}
        }
        __threadfence();
    }
    __syncthreads();
}

// full symmetric 128x128 Gram tile for k-chunk [k0,k0+KCc) via bf16-split mma
// 16 warps, each owns a 32x32 sub-tile
template <int KCc>
__device__ __forceinline__ void gram_tile(const float* __restrict__ F, int D,
                                          int k0, float* __restrict__ part,
                                          float* __restrict__ diag_out,
                                          unsigned* Hs, int t) {
    constexpr int S = KCc / 2 + 4;        // word stride; S%32==4 -> conflict-free
    constexpr int QPR = KCc / 4;          // float4 quads per row
    constexpr int QPT = NB * QPR / NT;
    constexpr int QSH = (KCc == 256) ? 6 : 5;
    unsigned* Ls = Hs + NB * S;

    {   // stage: load fp32, split into packed-bf16 hi/lo tiles (one CVT per elem)
        const float4* Fp = (const float4*)F;
        int D4 = D >> 2, kq0 = k0 >> 2;
#pragma unroll
        for (int l = 0; l < QPT; l++) {
            int qi = t + NT * l;
            int row = qi >> QSH, q = qi & (QPR - 1);
            float4 v = Fp[(size_t)row * D4 + kq0 + q];
            unsigned h0 = pack_bf16(v.x, v.y);
            unsigned h1 = pack_bf16(v.z, v.w);
            float lx = v.x - __uint_as_float(h0 << 16);
            float ly = v.y - __uint_as_float(h0 & 0xFFFF0000u);
            float lz = v.z - __uint_as_float(h1 << 16);
            float lw = v.w - __uint_as_float(h1 & 0xFFFF0000u);
            unsigned l0 = pack_bf16(lx, ly);
            unsigned l1 = pack_bf16(lz, lw);
            *(uint2*)&Hs[row * S + 2 * q] = make_uint2(h0, h1);
            *(uint2*)&Ls[row * S + 2 * q] = make_uint2(l0, l1);
        }
    }
    __syncthreads();

    int wid = t >> 5, lane = t & 31;
    int wm = wid & 3, wn = wid >> 2;      // warp tile: rows [32wm,+32), cols [32wn,+32)
    int grp = lane >> 2, tig = lane & 3;

    float c[2][4][4];
#pragma unroll
    for (int mt = 0; mt < 2; mt++)
#pragma unroll
        for (int nt = 0; nt < 4; nt++)
#pragma unroll
            for (int e = 0; e < 4; e++) c[mt][nt][e] = 0.f;

#pragma unroll
    for (int ks = 0; ks < KCc / 16; ks++) {
        int kb = ks * 8;                   // 8 bf16x2 words per k16 step
        unsigned ah[2][4], al[2][4];
#pragma unroll
        for (int mt = 0; mt < 2; mt++) {
            int r0 = wm * 32 + mt * 16 + grp;
            ah[mt][0] = Hs[r0 * S + kb + tig];
            ah[mt][1] = Hs[(r0 + 8) * S + kb + tig];
            ah[mt][2] = Hs[r0 * S + kb + tig + 4];
            ah[mt][3] = Hs[(r0 + 8) * S + kb + tig + 4];
            al[mt][0] = Ls[r0 * S + kb + tig];
            al[mt][1] = Ls[(r0 + 8) * S + kb + tig];
            al[mt][2] = Ls[r0 * S + kb + tig + 4];
            al[mt][3] = Ls[(r0 + 8) * S + kb + tig + 4];
        }
#pragma unroll
        for (int nt = 0; nt < 4; nt++) {
            int nr = wn * 32 + nt * 8 + grp;
            unsigned bh0 = Hs[nr * S + kb + tig];
            unsigned bh1 = Hs[nr * S + kb + tig + 4];
            unsigned bl0 = Ls[nr * S + kb + tig];
            unsigned bl1 = Ls[nr * S + kb + tig + 4];
#pragma unroll
            for (int mt = 0; mt < 2; mt++) {
                MMAB(c[mt][nt], ah[mt], bh0, bh1);   // hi*hi
                MMAB(c[mt][nt], ah[mt], bl0, bl1);   // hi*lo
                MMAB(c[mt][nt], al[mt], bh0, bh1);   // lo*hi
            }
        }
    }

    // epilogue: write tile + extract diagonal
    // c0=(r,2tig) c1=(r,2tig+1) c2=(r+8,2tig) c3=(r+8,2tig+1)
#pragma unroll
    for (int mt = 0; mt < 2; mt++)
#pragma unroll
        for (int nt = 0; nt < 4; nt++) {
            int row = wm * 32 + mt * 16 + grp;
            int col = wn * 32 + nt * 8 + 2 * tig;
            *(float2*)&part[row * NB + col] =
                make_float2(c[mt][nt][0], c[mt][nt][1]);
            *(float2*)&part[(row + 8) * NB + col] =
                make_float2(c[mt][nt][2], c[mt][nt][3]);
            if (col == row)          diag_out[row] = c[mt][nt][0];
            else if (col + 1 == row) diag_out[row] = c[mt][nt][1];
            if (col == row + 8)          diag_out[row + 8] = c[mt][nt][2];
            else if (col + 1 == row + 8) diag_out[row + 8] = c[mt][nt][3];
        }
}

__global__ __launch_bounds__(NT, 1)
void k_fused(const float* __restrict__ img, const float* __restrict__ lang,
             const float* __restrict__ temp, float* __restrict__ out) {
    extern __shared__ float Ts[];
    int bid = blockIdx.x;
    int t = threadIdx.x;

    // ================= PHASE 1: Gram partial via bf16-split mma.sync ========
    {
        int m = bid >> 5;            // 0 = image, 1 = lang
        int ch = bid & 31;
        if (m == 0)
            gram_tile<256>(img, D_IMG, ch * 256,
                           d_part_img + ch * NB * NB, &d_diag[0][ch][0],
                           (unsigned*)Ts, t);
        else
            gram_tile<128>(lang, D_LANG, ch * 128,
                           d_part_lang + ch * NB * NB, &d_diag[1][ch][0],
                           (unsigned*)Ts, t);
    }

    grid_bar(0);

    // ================= PHASE 2: norms + pre + row lse (4 rows per block) ====
    float* norm0 = Ts;           // [128] image norms
    float* norm1 = Ts + 128;     // [128] lang norms
    float* sred  = Ts + 256;     // [16] per-warp partials
    if (t < 256) {
        int mm = t >> 7, j = t & 127;
        float s = 0.f;
#pragma unroll 16
        for (int ci = 0; ci < NCH; ci++) s += d_diag[mm][ci][j];   // coalesced
        (mm ? norm1 : norm0)[j] = s;
    }
    float expT = __expf(temp[0]);
    __syncthreads();

    {
        int rr = t >> 7, j = t & 127;       // 4 rows per block
        int r = bid * 4 + rr;               // rows 0-255, exact
        int m = r >> 7, i = r & 127;
        const float* part = m ? d_part_lang : d_part_img;
        float g = 0.f;
#pragma unroll 16
        for (int ci = 0; ci < NCH; ci++) g += part[ci * NB * NB + i * NB + j];
        const float* nrm = m ? norm1 : norm0;
        float sq = nrm[i] + nrm[j] - 2.f * g;
        float pre = (j == i) ? 0.f : -sqrtf(fmaxf(sq, 0.f)) * expT;
        d_pre[m * NB * NB + i * NB + j] = pre;
        float e = __expf(pre);
#pragma unroll
        for (int o = 16; o; o >>= 1) e += __shfl_xor_sync(~0u, e, o);
        if ((t & 31) == 0) sred[t >> 5] = e;
        __syncthreads();
        if (j == 0) {
            int base = rr * 4;
            float s = sred[base] + sred[base + 1] + sred[base + 2] + sred[base + 3];
            d_lse[r] = __logf(s);
        }
    }

    grid_bar(1);

    // ================= PHASE 3: KL combine + column sum (2 cols per block) ==
    if (t < 256) {
        int half = t >> 7, i = t & 127;
        int col = bid * 2 + half;           // cols 0-127, exact
        float af = d_pre[i * NB + col] - d_lse[i];
        float ag = d_pre[NB * NB + i * NB + col] - d_lse[NB + i];
        float v = __expf(ag) * (ag - af);
#pragma unroll
        for (int o = 16; o; o >>= 1) v += __shfl_xor_sync(~0u, v, o);
        if ((i & 31) == 0) sred[t >> 5] = v;
    }
    __syncthreads();
    if (t < 256 && (t & 127) == 0) {
        int half = t >> 7;
        int base = half * 4;
        out[bid * 2 + half] =
            sred[base] + sred[base + 1] + sred[base + 2] + sred[base + 3];
    }
}

extern "C" void kernel_launch(void* const* d_in, const int* in_sizes, int n_in,
                              void* d_out, int out_size) {
    const float* img = (const float*)d_in[0];
    const float* lang = (const float*)d_in[1];
    const float* temp = (const float*)d_in[2];
    float* out = (float*)d_out;
    (void)in_sizes; (void)n_in; (void)out_size;

    cudaFuncSetAttribute(k_fused, cudaFuncAttributeMaxDynamicSharedMemorySize,
                         (int)SMEM_TOTAL);
    k_fused<<<GRID, NT, SMEM_TOTAL>>>(img, lang, temp, out);
}